// round 14
// baseline (speedup 1.0000x reference)
#include <cuda_runtime.h>
#include <cuda_bf16.h>
#include <math.h>
#include <stdint.h>

#define NMAX 50000
#define EMAX 800000
#define NEG_SLOPE 0.2f

// ---------------- static device scratch --------------------------------------
__device__ float g_feat[NMAX * 128];   // current layer fc output [N,H*D]
__device__ float g_rstA[NMAX * 128];   // layer0 output (h1)
__device__ float g_rstB[NMAX * 128];   // layer1 output (h2)
__device__ float g_el[NMAX * 4];
__device__ float g_er[NMAX * 4];
__device__ float g_feat2[NMAX * 4];    // layer2 fc output
__device__ int   g_count[NMAX];
__device__ int   g_rowptr[NMAX + 1];
__device__ int   g_cursor[NMAX];
__device__ int   g_csrsrc[EMAX];

// ---------------- tf32 helpers ------------------------------------------------
__device__ __forceinline__ uint32_t f2tf32(float x) {
    uint32_t r;
    asm("cvt.rna.tf32.f32 %0, %1;" : "=r"(r) : "f"(x));
    return r;
}
// d += A(16x8) * B(8x8), tf32, m16n8k8 standard fragment layout
__device__ __forceinline__ void mma_tf32_k8(float* d, const uint32_t* a,
                                            uint32_t b0, uint32_t b1) {
    asm("mma.sync.aligned.m16n8k8.row.col.f32.tf32.tf32.f32 "
        "{%0,%1,%2,%3}, {%4,%5,%6,%7}, {%8,%9}, {%0,%1,%2,%3};"
        : "+f"(d[0]), "+f"(d[1]), "+f"(d[2]), "+f"(d[3])
        : "r"(a[0]), "r"(a[1]), "r"(a[2]), "r"(a[3]), "r"(b0), "r"(b1));
}

// ---------------- CSR build ---------------------------------------------------
__global__ void count_kernel(const int* __restrict__ dst, int* __restrict__ count,
                             int E) {
    int e = blockIdx.x * blockDim.x + threadIdx.x;
    if (e < E) atomicAdd(&count[dst[e]], 1);
}

__global__ void scan_kernel(const int* __restrict__ count,
                            int* __restrict__ rowptr,
                            int* __restrict__ cursor, int n) {
    __shared__ int ssum[1024];
    int t = threadIdx.x;
    int chunk = (n + 1023) >> 10;
    int begin = t * chunk;
    int end = min(begin + chunk, n);
    int sum = 0;
    for (int i = begin; i < end; i++) sum += count[i];
    ssum[t] = sum;
    __syncthreads();
    for (int off = 1; off < 1024; off <<= 1) {
        int v = (t >= off) ? ssum[t - off] : 0;
        __syncthreads();
        ssum[t] += v;
        __syncthreads();
    }
    int prefix = (t == 0) ? 0 : ssum[t - 1];
    for (int i = begin; i < end; i++) {
        rowptr[i] = prefix;
        cursor[i] = prefix;
        prefix += count[i];
    }
    if (t == 0) rowptr[n] = ssum[1023];
}

__global__ void fill_csr_kernel(const int* __restrict__ src,
                                const int* __restrict__ dst,
                                int* __restrict__ cursor,
                                int* __restrict__ csrsrc, int E) {
    int e = blockIdx.x * blockDim.x + threadIdx.x;
    if (e < E) {
        int pos = atomicAdd(&cursor[dst[e]], 1);
        csrsrc[pos] = src[e];
    }
}

// ---------------- tensor-core fc + attention projections (layers 0,1) --------
#define A_STRIDE 36
#define B_STRIDE 136
#define SM_A_HI 0
#define SM_A_LO (64 * A_STRIDE)                     // 2304
#define SM_B_HI (2 * 64 * A_STRIDE)                 // 4608
#define SM_B_LO (SM_B_HI + 32 * B_STRIDE)           // 8960
#define SM_TOTAL_F (SM_B_LO + 32 * B_STRIDE)        // 13312 floats = 53248 B

template <int K>
__global__ void gemm_attn_tc(const float* __restrict__ h,
                             const float* __restrict__ W,
                             const float* __restrict__ al,
                             const float* __restrict__ ar,
                             float* __restrict__ feat,
                             float* __restrict__ el,
                             float* __restrict__ er,
                             int N) {
    extern __shared__ uint32_t sm[];
    int t = threadIdx.x;
    int node0 = blockIdx.x * 64;
    int lane = t & 31;
    int wid = t >> 5;
    int gid = lane >> 2;      // 0..7
    int tig = lane & 3;       // 0..3
    int warp_m = wid >> 2;    // 0..1
    int warp_n = wid & 3;     // 0..3
    int rm = warp_m * 32;
    int cn = warp_n * 32;

    float acc[2][4][4];
#pragma unroll
    for (int a = 0; a < 2; a++)
#pragma unroll
        for (int b = 0; b < 4; b++)
#pragma unroll
            for (int q = 0; q < 4; q++) acc[a][b][q] = 0.0f;

    for (int kc = 0; kc < K; kc += 32) {
        // ---- stage A (h): 64 rows x 32 k, hi/lo ----
#pragma unroll
        for (int it = 0; it < 2; it++) {
            int idx = t + it * 256;          // 0..511 float4 slots
            int row = idx >> 3;
            int j4 = (idx & 7) << 2;
            float4 v = make_float4(0.f, 0.f, 0.f, 0.f);
            if (node0 + row < N)
                v = *(const float4*)(h + (node0 + row) * K + kc + j4);
            uint32_t hx = f2tf32(v.x), hy = f2tf32(v.y);
            uint32_t hz = f2tf32(v.z), hw = f2tf32(v.w);
            uint32_t lx = f2tf32(v.x - __uint_as_float(hx));
            uint32_t ly = f2tf32(v.y - __uint_as_float(hy));
            uint32_t lz = f2tf32(v.z - __uint_as_float(hz));
            uint32_t lw = f2tf32(v.w - __uint_as_float(hw));
            int base = row * A_STRIDE + j4;
            sm[SM_A_HI + base + 0] = hx; sm[SM_A_HI + base + 1] = hy;
            sm[SM_A_HI + base + 2] = hz; sm[SM_A_HI + base + 3] = hw;
            sm[SM_A_LO + base + 0] = lx; sm[SM_A_LO + base + 1] = ly;
            sm[SM_A_LO + base + 2] = lz; sm[SM_A_LO + base + 3] = lw;
        }
        // ---- stage B (W): 32 k x 128 cols, hi/lo ----
#pragma unroll
        for (int it = 0; it < 4; it++) {
            int idx = t + it * 256;          // 0..1023 float4 slots
            int kk = idx >> 5;
            int c4 = (idx & 31) << 2;
            float4 v = *(const float4*)(W + (kc + kk) * 128 + c4);
            uint32_t hx = f2tf32(v.x), hy = f2tf32(v.y);
            uint32_t hz = f2tf32(v.z), hw = f2tf32(v.w);
            uint32_t lx = f2tf32(v.x - __uint_as_float(hx));
            uint32_t ly = f2tf32(v.y - __uint_as_float(hy));
            uint32_t lz = f2tf32(v.z - __uint_as_float(hz));
            uint32_t lw = f2tf32(v.w - __uint_as_float(hw));
            int base = kk * B_STRIDE + c4;
            sm[SM_B_HI + base + 0] = hx; sm[SM_B_HI + base + 1] = hy;
            sm[SM_B_HI + base + 2] = hz; sm[SM_B_HI + base + 3] = hw;
            sm[SM_B_LO + base + 0] = lx; sm[SM_B_LO + base + 1] = ly;
            sm[SM_B_LO + base + 2] = lz; sm[SM_B_LO + base + 3] = lw;
        }
        __syncthreads();

        // ---- 4 k8-steps over this 32-k chunk ----
#pragma unroll
        for (int ks = 0; ks < 4; ks++) {
            int kb = ks * 8;
            uint32_t ahi[2][4], alo[2][4];
#pragma unroll
            for (int tm = 0; tm < 2; tm++) {
                int r0 = (rm + tm * 16 + gid) * A_STRIDE + kb;
                int r8 = r0 + 8 * A_STRIDE;
                ahi[tm][0] = sm[SM_A_HI + r0 + tig];
                ahi[tm][1] = sm[SM_A_HI + r8 + tig];
                ahi[tm][2] = sm[SM_A_HI + r0 + tig + 4];
                ahi[tm][3] = sm[SM_A_HI + r8 + tig + 4];
                alo[tm][0] = sm[SM_A_LO + r0 + tig];
                alo[tm][1] = sm[SM_A_LO + r8 + tig];
                alo[tm][2] = sm[SM_A_LO + r0 + tig + 4];
                alo[tm][3] = sm[SM_A_LO + r8 + tig + 4];
            }
#pragma unroll
            for (int tn = 0; tn < 4; tn++) {
                int b0i = (kb + tig) * B_STRIDE + cn + tn * 8 + gid;
                int b1i = (kb + tig + 4) * B_STRIDE + cn + tn * 8 + gid;
                uint32_t bh0 = sm[SM_B_HI + b0i];
                uint32_t bh1 = sm[SM_B_HI + b1i];
                uint32_t bl0 = sm[SM_B_LO + b0i];
                uint32_t bl1 = sm[SM_B_LO + b1i];
#pragma unroll
                for (int tm = 0; tm < 2; tm++) {
                    mma_tf32_k8(acc[tm][tn], ahi[tm], bh0, bh1);
                    mma_tf32_k8(acc[tm][tn], ahi[tm], bl0, bl1);
                    mma_tf32_k8(acc[tm][tn], alo[tm], bh0, bh1);
                }
            }
        }
        __syncthreads();
    }

    // ---- epilogue: store feat, compute el/er (head = warp_n) ----
    int head = warp_n;
    float alv[4][2], arv[4][2];
#pragma unroll
    for (int tn = 0; tn < 4; tn++) {
#pragma unroll
        for (int j = 0; j < 2; j++) {
            int cc = tn * 8 + tig * 2 + j;
            alv[tn][j] = al[head * 32 + cc];
            arv[tn][j] = ar[head * 32 + cc];
        }
    }
#pragma unroll
    for (int tm = 0; tm < 2; tm++) {
#pragma unroll
        for (int half = 0; half < 2; half++) {
            int node = node0 + rm + tm * 16 + gid + half * 8;
            float pa = 0.f, pb = 0.f;
#pragma unroll
            for (int tn = 0; tn < 4; tn++) {
                pa += acc[tm][tn][half * 2 + 0] * alv[tn][0]
                    + acc[tm][tn][half * 2 + 1] * alv[tn][1];
                pb += acc[tm][tn][half * 2 + 0] * arv[tn][0]
                    + acc[tm][tn][half * 2 + 1] * arv[tn][1];
            }
            pa += __shfl_down_sync(0xFFFFFFFFu, pa, 2, 4);
            pa += __shfl_down_sync(0xFFFFFFFFu, pa, 1, 4);
            pb += __shfl_down_sync(0xFFFFFFFFu, pb, 2, 4);
            pb += __shfl_down_sync(0xFFFFFFFFu, pb, 1, 4);
            if (node < N) {
#pragma unroll
                for (int tn = 0; tn < 4; tn++) {
                    float2 st = make_float2(acc[tm][tn][half * 2 + 0],
                                            acc[tm][tn][half * 2 + 1]);
                    *(float2*)(feat + node * 128 + cn + tn * 8 + tig * 2) = st;
                }
                if (tig == 0) {
                    el[node * 4 + head] = pa;
                    er[node * 4 + head] = pb;
                }
            }
        }
    }
}

// ---------------- layer2 fc (K=128 -> OUT=4, H=1), one warp per node ---------
__global__ void gemm2_kernel(const float* __restrict__ h,
                             const float* __restrict__ W,
                             const float* __restrict__ al,
                             const float* __restrict__ ar,
                             float* __restrict__ feat2,
                             float* __restrict__ el,
                             float* __restrict__ er,
                             int N) {
    int warp = (blockIdx.x * blockDim.x + threadIdx.x) >> 5;
    int lane = threadIdx.x & 31;
    if (warp >= N) return;

    float a0 = 0.f, a1 = 0.f, a2 = 0.f, a3 = 0.f;
#pragma unroll
    for (int i = 0; i < 4; i++) {
        int k = lane + 32 * i;
        float hv = h[warp * 128 + k];
        const float4 w = *(const float4*)(W + k * 4);
        a0 += hv * w.x; a1 += hv * w.y; a2 += hv * w.z; a3 += hv * w.w;
    }
#pragma unroll
    for (int o = 16; o > 0; o >>= 1) {
        a0 += __shfl_xor_sync(0xFFFFFFFFu, a0, o);
        a1 += __shfl_xor_sync(0xFFFFFFFFu, a1, o);
        a2 += __shfl_xor_sync(0xFFFFFFFFu, a2, o);
        a3 += __shfl_xor_sync(0xFFFFFFFFu, a3, o);
    }
    if (lane == 0) {
        feat2[warp * 4 + 0] = a0;
        feat2[warp * 4 + 1] = a1;
        feat2[warp * 4 + 2] = a2;
        feat2[warp * 4 + 3] = a3;
        el[warp] = a0 * al[0] + a1 * al[1] + a2 * al[2] + a3 * al[3];
        er[warp] = a0 * ar[0] + a1 * ar[1] + a2 * ar[2] + a3 * ar[3];
    }
}

// ---------------- fused aggregation (layers 0,1): TWO warps per dst -----------
// 8 warps/block, 4 nodes/block. Warp half h takes edges [h*dh_adj...] of its
// node (contiguous split). R12 4-way inner loop. Half-1 writes partials to
// smem; half-0 combines + epilogue.
__global__ void aggr_warp2_kernel(const int* __restrict__ rowptr,
                                  const int* __restrict__ csrsrc,
                                  const float* __restrict__ el,
                                  const float* __restrict__ er,
                                  const float* __restrict__ feat,
                                  const float* __restrict__ bias,
                                  const float* __restrict__ resid,
                                  float* __restrict__ rst,
                                  int N, int applyAct) {
    __shared__ float s_acc[4][128];
    __shared__ float s_sexp[4][32];

    int t = threadIdx.x;
    int lane = t & 31;
    int wid = t >> 5;
    int node_local = wid >> 1;     // 0..3
    int half = wid & 1;
    int di = blockIdx.x * 4 + node_local;

    float4 acc = make_float4(0.f, 0.f, 0.f, 0.f);
    float sexp = 0.0f;
    int head = lane >> 3;

    if (di < N) {
        int row0 = rowptr[di];
        int deg = rowptr[di + 1] - row0;
        int dh = (deg + 1) >> 1;
        int ebeg = half ? dh : 0;
        int eend = half ? deg : dh;
        float er_l = (lane < 4) ? er[di * 4 + lane] : 0.0f;

        int e = ebeg;
        for (; e + 4 <= eend; e += 4) {
            int si0 = csrsrc[row0 + e];
            int si1 = csrsrc[row0 + e + 1];
            int si2 = csrsrc[row0 + e + 2];
            int si3 = csrsrc[row0 + e + 3];
            float x0 = 0.f, x1 = 0.f, x2 = 0.f, x3 = 0.f;
            if (lane < 4) {
                float v0 = el[si0 * 4 + lane] + er_l;
                float v1 = el[si1 * 4 + lane] + er_l;
                float v2 = el[si2 * 4 + lane] + er_l;
                float v3 = el[si3 * 4 + lane] + er_l;
                v0 = (v0 > 0.f) ? v0 : NEG_SLOPE * v0;
                v1 = (v1 > 0.f) ? v1 : NEG_SLOPE * v1;
                v2 = (v2 > 0.f) ? v2 : NEG_SLOPE * v2;
                v3 = (v3 > 0.f) ? v3 : NEG_SLOPE * v3;
                x0 = __expf(v0); x1 = __expf(v1);
                x2 = __expf(v2); x3 = __expf(v3);
            }
            float exa = __shfl_sync(0xFFFFFFFFu, x0, head);
            float exb = __shfl_sync(0xFFFFFFFFu, x1, head);
            float exc = __shfl_sync(0xFFFFFFFFu, x2, head);
            float exd = __shfl_sync(0xFFFFFFFFu, x3, head);
            const float4 fa = *(const float4*)(feat + si0 * 128 + lane * 4);
            const float4 fb = *(const float4*)(feat + si1 * 128 + lane * 4);
            const float4 fc = *(const float4*)(feat + si2 * 128 + lane * 4);
            const float4 fd = *(const float4*)(feat + si3 * 128 + lane * 4);
            acc.x += exa * fa.x + exb * fb.x + exc * fc.x + exd * fd.x;
            acc.y += exa * fa.y + exb * fb.y + exc * fc.y + exd * fd.y;
            acc.z += exa * fa.z + exb * fb.z + exc * fc.z + exd * fd.z;
            acc.w += exa * fa.w + exb * fb.w + exc * fc.w + exd * fd.w;
            sexp += exa + exb + exc + exd;
        }
        for (; e < eend; e++) {
            int si = csrsrc[row0 + e];
            float ex4 = 0.f;
            if (lane < 4) {
                float v = el[si * 4 + lane] + er_l;
                v = (v > 0.f) ? v : NEG_SLOPE * v;
                ex4 = __expf(v);
            }
            float ex = __shfl_sync(0xFFFFFFFFu, ex4, head);
            const float4 f = *(const float4*)(feat + si * 128 + lane * 4);
            acc.x += ex * f.x; acc.y += ex * f.y;
            acc.z += ex * f.z; acc.w += ex * f.w;
            sexp += ex;
        }
    }

    // half-1 publishes partials
    if (half) {
        *(float4*)(&s_acc[node_local][lane * 4]) = acc;
        s_sexp[node_local][lane] = sexp;
    }
    __syncthreads();

    if (half == 0 && di < N) {
        const float4 p = *(const float4*)(&s_acc[node_local][lane * 4]);
        acc.x += p.x; acc.y += p.y; acc.z += p.z; acc.w += p.w;
        sexp += s_sexp[node_local][lane];

        float inv = (sexp > 0.0f) ? 1.0f / sexp : 0.0f;
        int idx = di * 128 + lane * 4;
        const float4 b4 = *(const float4*)(bias + lane * 4);
        float4 v = make_float4(acc.x * inv + b4.x, acc.y * inv + b4.y,
                               acc.z * inv + b4.z, acc.w * inv + b4.w);
        if (resid) {
            const float4 r4 = *(const float4*)(resid + idx);
            v.x += r4.x; v.y += r4.y; v.z += r4.z; v.w += r4.w;
        }
        if (applyAct) {
            v.x = (v.x > 0.f) ? v.x : (__expf(v.x) - 1.0f);
            v.y = (v.y > 0.f) ? v.y : (__expf(v.y) - 1.0f);
            v.z = (v.z > 0.f) ? v.z : (__expf(v.z) - 1.0f);
            v.w = (v.w > 0.f) ? v.w : (__expf(v.w) - 1.0f);
        }
        *(float4*)(rst + idx) = v;
    }
}

// ---------------- fused aggregation (layer 2, H=1, D=4) ----------------------
__global__ void aggr2_kernel(const int* __restrict__ rowptr,
                             const int* __restrict__ csrsrc,
                             const float* __restrict__ el,
                             const float* __restrict__ er,
                             const float* __restrict__ feat2,
                             const float* __restrict__ bias,
                             float* __restrict__ out,
                             int N) {
    int di = (blockIdx.x * blockDim.x + threadIdx.x) >> 5;
    int lane = threadIdx.x & 31;
    if (di >= N) return;

    int row0 = rowptr[di];
    int deg = rowptr[di + 1] - row0;
    float erd = er[di];

    float a0 = 0.f, a1 = 0.f, a2 = 0.f, a3 = 0.f, sexp = 0.f;
    for (int e = lane; e < deg; e += 32) {
        int si = csrsrc[row0 + e];
        float v = el[si] + erd;
        v = (v > 0.f) ? v : NEG_SLOPE * v;
        float ex = __expf(v);
        const float4 f = *(const float4*)(feat2 + si * 4);
        a0 += ex * f.x; a1 += ex * f.y; a2 += ex * f.z; a3 += ex * f.w;
        sexp += ex;
    }
#pragma unroll
    for (int o = 16; o > 0; o >>= 1) {
        a0 += __shfl_xor_sync(0xFFFFFFFFu, a0, o);
        a1 += __shfl_xor_sync(0xFFFFFFFFu, a1, o);
        a2 += __shfl_xor_sync(0xFFFFFFFFu, a2, o);
        a3 += __shfl_xor_sync(0xFFFFFFFFu, a3, o);
        sexp += __shfl_xor_sync(0xFFFFFFFFu, sexp, o);
    }
    if (lane == 0) {
        float inv = (sexp > 0.0f) ? 1.0f / sexp : 0.0f;
        out[di * 4 + 0] = a0 * inv + bias[0];
        out[di * 4 + 1] = a1 * inv + bias[1];
        out[di * 4 + 2] = a2 * inv + bias[2];
        out[di * 4 + 3] = a3 * inv + bias[3];
    }
}

// ---------------- host launcher ----------------------------------------------
extern "C" void kernel_launch(void* const* d_in, const int* in_sizes, int n_in,
                              void* d_out, int out_size) {
    const float* x   = (const float*)d_in[0];
    const int*   src = (const int*)d_in[1];
    const int*   dst = (const int*)d_in[2];
    const float* W0  = (const float*)d_in[3];
    const float* al0 = (const float*)d_in[4];
    const float* ar0 = (const float*)d_in[5];
    const float* b0  = (const float*)d_in[6];
    const float* W1  = (const float*)d_in[7];
    const float* al1 = (const float*)d_in[8];
    const float* ar1 = (const float*)d_in[9];
    const float* b1  = (const float*)d_in[10];
    const float* W2  = (const float*)d_in[11];
    const float* al2 = (const float*)d_in[12];
    const float* ar2 = (const float*)d_in[13];
    const float* b2  = (const float*)d_in[14];

    int N = in_sizes[0] / 64;
    int E = in_sizes[1];

    float *feat, *rstA, *rstB, *el, *er, *feat2;
    int *count, *rowptr, *cursor, *csrsrc;
    cudaGetSymbolAddress((void**)&feat,   g_feat);
    cudaGetSymbolAddress((void**)&rstA,   g_rstA);
    cudaGetSymbolAddress((void**)&rstB,   g_rstB);
    cudaGetSymbolAddress((void**)&el,     g_el);
    cudaGetSymbolAddress((void**)&er,     g_er);
    cudaGetSymbolAddress((void**)&feat2,  g_feat2);
    cudaGetSymbolAddress((void**)&count,  g_count);
    cudaGetSymbolAddress((void**)&rowptr, g_rowptr);
    cudaGetSymbolAddress((void**)&cursor, g_cursor);
    cudaGetSymbolAddress((void**)&csrsrc, g_csrsrc);

    float* out = (float*)d_out;

    const int TB = 256;
    int gridE = (E + TB - 1) / TB;
    int gridGemm = (N + 63) / 64;
    int gridWarpN = (N * 32 + TB - 1) / TB;   // warp per node
    int gridAggr2w = (N + 3) / 4;             // 2 warps per node, 4 nodes/block

    int smemTC = SM_TOTAL_F * sizeof(uint32_t);   // 53248 B
    cudaFuncSetAttribute(gemm_attn_tc<64>,
                         cudaFuncAttributeMaxDynamicSharedMemorySize, smemTC);
    cudaFuncSetAttribute(gemm_attn_tc<128>,
                         cudaFuncAttributeMaxDynamicSharedMemorySize, smemTC);

    // ---------- fork: CSR build in parallel with layer-0 gemm ----------
    cudaStream_t s2 = 0;
    cudaEvent_t evA = 0, evB = 0;
    bool forked =
        (cudaStreamCreateWithFlags(&s2, cudaStreamNonBlocking) == cudaSuccess) &&
        (cudaEventCreateWithFlags(&evA, cudaEventDisableTiming) == cudaSuccess) &&
        (cudaEventCreateWithFlags(&evB, cudaEventDisableTiming) == cudaSuccess);

    if (forked) {
        cudaEventRecord(evA, 0);
        cudaStreamWaitEvent(s2, evA, 0);
        cudaMemsetAsync(count, 0, N * sizeof(int), s2);
        count_kernel<<<gridE, TB, 0, s2>>>(dst, count, E);
        scan_kernel<<<1, 1024, 0, s2>>>(count, rowptr, cursor, N);
        fill_csr_kernel<<<gridE, TB, 0, s2>>>(src, dst, cursor, csrsrc, E);
        cudaEventRecord(evB, s2);

        gemm_attn_tc<64><<<gridGemm, 256, smemTC>>>(x, W0, al0, ar0, feat, el, er, N);
        cudaStreamWaitEvent(0, evB, 0);
    } else {
        cudaMemsetAsync(count, 0, N * sizeof(int));
        count_kernel<<<gridE, TB>>>(dst, count, E);
        scan_kernel<<<1, 1024>>>(count, rowptr, cursor, N);
        fill_csr_kernel<<<gridE, TB>>>(src, dst, cursor, csrsrc, E);
        gemm_attn_tc<64><<<gridGemm, 256, smemTC>>>(x, W0, al0, ar0, feat, el, er, N);
    }

    // ---------- layer 0 aggregation ----------
    aggr_warp2_kernel<<<gridAggr2w, TB>>>(rowptr, csrsrc, el, er, feat, b0, nullptr, rstA, N, 1);

    // ---------- layer 1 (K=128, residual) ----------
    gemm_attn_tc<128><<<gridGemm, 256, smemTC>>>(rstA, W1, al1, ar1, feat, el, er, N);
    aggr_warp2_kernel<<<gridAggr2w, TB>>>(rowptr, csrsrc, el, er, feat, b1, rstA, rstB, N, 1);

    // ---------- layer 2 (K=128 -> 4, H=1) ----------
    gemm2_kernel<<<gridWarpN, TB>>>(rstB, W2, al2, ar2, feat2, el, er, N);
    aggr2_kernel<<<gridWarpN, TB>>>(rowptr, csrsrc, el, er, feat2, b2, out, N);
}

// round 15
// speedup vs baseline: 1.0980x; 1.0980x over previous
#include <cuda_runtime.h>
#include <cuda_bf16.h>
#include <math.h>
#include <stdint.h>

#define NMAX 50000
#define EMAX 800000
#define NEG_SLOPE 0.2f

// ---------------- static device scratch --------------------------------------
__device__ float g_feat[NMAX * 128];   // current layer fc output [N,H*D]
__device__ float g_rstA[NMAX * 128];   // layer0 output (h1)
__device__ float g_rstB[NMAX * 128];   // layer1 output (h2)
__device__ float g_el[NMAX * 4];
__device__ float g_er[NMAX * 4];
__device__ float g_feat2[NMAX * 4];    // layer2 fc output
__device__ int   g_count[NMAX];
__device__ int   g_rowptr[NMAX + 1];
__device__ int   g_cursor[NMAX];
__device__ int   g_csrsrc[EMAX];

// ---------------- tf32 helpers ------------------------------------------------
__device__ __forceinline__ uint32_t f2tf32(float x) {
    uint32_t r;
    asm("cvt.rna.tf32.f32 %0, %1;" : "=r"(r) : "f"(x));
    return r;
}
// d += A(16x8) * B(8x8), tf32, m16n8k8 standard fragment layout
__device__ __forceinline__ void mma_tf32_k8(float* d, const uint32_t* a,
                                            uint32_t b0, uint32_t b1) {
    asm("mma.sync.aligned.m16n8k8.row.col.f32.tf32.tf32.f32 "
        "{%0,%1,%2,%3}, {%4,%5,%6,%7}, {%8,%9}, {%0,%1,%2,%3};"
        : "+f"(d[0]), "+f"(d[1]), "+f"(d[2]), "+f"(d[3])
        : "r"(a[0]), "r"(a[1]), "r"(a[2]), "r"(a[3]), "r"(b0), "r"(b1));
}

// ---------------- CSR build ---------------------------------------------------
__global__ void count_kernel(const int* __restrict__ dst, int* __restrict__ count,
                             int E) {
    int e = blockIdx.x * blockDim.x + threadIdx.x;
    if (e < E) atomicAdd(&count[dst[e]], 1);
}

__global__ void scan_kernel(const int* __restrict__ count,
                            int* __restrict__ rowptr,
                            int* __restrict__ cursor, int n) {
    __shared__ int ssum[1024];
    int t = threadIdx.x;
    int chunk = (n + 1023) >> 10;
    int begin = t * chunk;
    int end = min(begin + chunk, n);
    int sum = 0;
    for (int i = begin; i < end; i++) sum += count[i];
    ssum[t] = sum;
    __syncthreads();
    for (int off = 1; off < 1024; off <<= 1) {
        int v = (t >= off) ? ssum[t - off] : 0;
        __syncthreads();
        ssum[t] += v;
        __syncthreads();
    }
    int prefix = (t == 0) ? 0 : ssum[t - 1];
    for (int i = begin; i < end; i++) {
        rowptr[i] = prefix;
        cursor[i] = prefix;
        prefix += count[i];
    }
    if (t == 0) rowptr[n] = ssum[1023];
}

__global__ void fill_csr_kernel(const int* __restrict__ src,
                                const int* __restrict__ dst,
                                int* __restrict__ cursor,
                                int* __restrict__ csrsrc, int E) {
    int e = blockIdx.x * blockDim.x + threadIdx.x;
    if (e < E) {
        int pos = atomicAdd(&cursor[dst[e]], 1);
        csrsrc[pos] = src[e];
    }
}

// ---------------- tensor-core fc + attention projections (layers 0,1) --------
// Node range [base, nEnd). base must be a multiple of 64.
#define A_STRIDE 36
#define B_STRIDE 136
#define SM_A_HI 0
#define SM_A_LO (64 * A_STRIDE)                     // 2304
#define SM_B_HI (2 * 64 * A_STRIDE)                 // 4608
#define SM_B_LO (SM_B_HI + 32 * B_STRIDE)           // 8960
#define SM_TOTAL_F (SM_B_LO + 32 * B_STRIDE)        // 13312 floats = 53248 B

template <int K>
__global__ void gemm_attn_tc(const float* __restrict__ h,
                             const float* __restrict__ W,
                             const float* __restrict__ al,
                             const float* __restrict__ ar,
                             float* __restrict__ feat,
                             float* __restrict__ el,
                             float* __restrict__ er,
                             int base, int nEnd) {
    extern __shared__ uint32_t sm[];
    int t = threadIdx.x;
    int node0 = base + blockIdx.x * 64;
    int lane = t & 31;
    int wid = t >> 5;
    int gid = lane >> 2;      // 0..7
    int tig = lane & 3;       // 0..3
    int warp_m = wid >> 2;    // 0..1
    int warp_n = wid & 3;     // 0..3
    int rm = warp_m * 32;
    int cn = warp_n * 32;

    float acc[2][4][4];
#pragma unroll
    for (int a = 0; a < 2; a++)
#pragma unroll
        for (int b = 0; b < 4; b++)
#pragma unroll
            for (int q = 0; q < 4; q++) acc[a][b][q] = 0.0f;

    for (int kc = 0; kc < K; kc += 32) {
        // ---- stage A (h): 64 rows x 32 k, hi/lo ----
#pragma unroll
        for (int it = 0; it < 2; it++) {
            int idx = t + it * 256;          // 0..511 float4 slots
            int row = idx >> 3;
            int j4 = (idx & 7) << 2;
            float4 v = make_float4(0.f, 0.f, 0.f, 0.f);
            if (node0 + row < nEnd)
                v = *(const float4*)(h + (node0 + row) * K + kc + j4);
            uint32_t hx = f2tf32(v.x), hy = f2tf32(v.y);
            uint32_t hz = f2tf32(v.z), hw = f2tf32(v.w);
            uint32_t lx = f2tf32(v.x - __uint_as_float(hx));
            uint32_t ly = f2tf32(v.y - __uint_as_float(hy));
            uint32_t lz = f2tf32(v.z - __uint_as_float(hz));
            uint32_t lw = f2tf32(v.w - __uint_as_float(hw));
            int bse = row * A_STRIDE + j4;
            sm[SM_A_HI + bse + 0] = hx; sm[SM_A_HI + bse + 1] = hy;
            sm[SM_A_HI + bse + 2] = hz; sm[SM_A_HI + bse + 3] = hw;
            sm[SM_A_LO + bse + 0] = lx; sm[SM_A_LO + bse + 1] = ly;
            sm[SM_A_LO + bse + 2] = lz; sm[SM_A_LO + bse + 3] = lw;
        }
        // ---- stage B (W): 32 k x 128 cols, hi/lo ----
#pragma unroll
        for (int it = 0; it < 4; it++) {
            int idx = t + it * 256;          // 0..1023 float4 slots
            int kk = idx >> 5;
            int c4 = (idx & 31) << 2;
            float4 v = *(const float4*)(W + (kc + kk) * 128 + c4);
            uint32_t hx = f2tf32(v.x), hy = f2tf32(v.y);
            uint32_t hz = f2tf32(v.z), hw = f2tf32(v.w);
            uint32_t lx = f2tf32(v.x - __uint_as_float(hx));
            uint32_t ly = f2tf32(v.y - __uint_as_float(hy));
            uint32_t lz = f2tf32(v.z - __uint_as_float(hz));
            uint32_t lw = f2tf32(v.w - __uint_as_float(hw));
            int bse = kk * B_STRIDE + c4;
            sm[SM_B_HI + bse + 0] = hx; sm[SM_B_HI + bse + 1] = hy;
            sm[SM_B_HI + bse + 2] = hz; sm[SM_B_HI + bse + 3] = hw;
            sm[SM_B_LO + bse + 0] = lx; sm[SM_B_LO + bse + 1] = ly;
            sm[SM_B_LO + bse + 2] = lz; sm[SM_B_LO + bse + 3] = lw;
        }
        __syncthreads();

        // ---- 4 k8-steps over this 32-k chunk ----
#pragma unroll
        for (int ks = 0; ks < 4; ks++) {
            int kb = ks * 8;
            uint32_t ahi[2][4], alo[2][4];
#pragma unroll
            for (int tm = 0; tm < 2; tm++) {
                int r0 = (rm + tm * 16 + gid) * A_STRIDE + kb;
                int r8 = r0 + 8 * A_STRIDE;
                ahi[tm][0] = sm[SM_A_HI + r0 + tig];
                ahi[tm][1] = sm[SM_A_HI + r8 + tig];
                ahi[tm][2] = sm[SM_A_HI + r0 + tig + 4];
                ahi[tm][3] = sm[SM_A_HI + r8 + tig + 4];
                alo[tm][0] = sm[SM_A_LO + r0 + tig];
                alo[tm][1] = sm[SM_A_LO + r8 + tig];
                alo[tm][2] = sm[SM_A_LO + r0 + tig + 4];
                alo[tm][3] = sm[SM_A_LO + r8 + tig + 4];
            }
#pragma unroll
            for (int tn = 0; tn < 4; tn++) {
                int b0i = (kb + tig) * B_STRIDE + cn + tn * 8 + gid;
                int b1i = (kb + tig + 4) * B_STRIDE + cn + tn * 8 + gid;
                uint32_t bh0 = sm[SM_B_HI + b0i];
                uint32_t bh1 = sm[SM_B_HI + b1i];
                uint32_t bl0 = sm[SM_B_LO + b0i];
                uint32_t bl1 = sm[SM_B_LO + b1i];
#pragma unroll
                for (int tm = 0; tm < 2; tm++) {
                    mma_tf32_k8(acc[tm][tn], ahi[tm], bh0, bh1);
                    mma_tf32_k8(acc[tm][tn], ahi[tm], bl0, bl1);
                    mma_tf32_k8(acc[tm][tn], alo[tm], bh0, bh1);
                }
            }
        }
        __syncthreads();
    }

    // ---- epilogue: store feat, compute el/er (head = warp_n) ----
    int head = warp_n;
    float alv[4][2], arv[4][2];
#pragma unroll
    for (int tn = 0; tn < 4; tn++) {
#pragma unroll
        for (int j = 0; j < 2; j++) {
            int cc = tn * 8 + tig * 2 + j;
            alv[tn][j] = al[head * 32 + cc];
            arv[tn][j] = ar[head * 32 + cc];
        }
    }
#pragma unroll
    for (int tm = 0; tm < 2; tm++) {
#pragma unroll
        for (int half = 0; half < 2; half++) {
            int node = node0 + rm + tm * 16 + gid + half * 8;
            float pa = 0.f, pb = 0.f;
#pragma unroll
            for (int tn = 0; tn < 4; tn++) {
                pa += acc[tm][tn][half * 2 + 0] * alv[tn][0]
                    + acc[tm][tn][half * 2 + 1] * alv[tn][1];
                pb += acc[tm][tn][half * 2 + 0] * arv[tn][0]
                    + acc[tm][tn][half * 2 + 1] * arv[tn][1];
            }
            pa += __shfl_down_sync(0xFFFFFFFFu, pa, 2, 4);
            pa += __shfl_down_sync(0xFFFFFFFFu, pa, 1, 4);
            pb += __shfl_down_sync(0xFFFFFFFFu, pb, 2, 4);
            pb += __shfl_down_sync(0xFFFFFFFFu, pb, 1, 4);
            if (node < nEnd) {
#pragma unroll
                for (int tn = 0; tn < 4; tn++) {
                    float2 st = make_float2(acc[tm][tn][half * 2 + 0],
                                            acc[tm][tn][half * 2 + 1]);
                    *(float2*)(feat + node * 128 + cn + tn * 8 + tig * 2) = st;
                }
                if (tig == 0) {
                    el[node * 4 + head] = pa;
                    er[node * 4 + head] = pb;
                }
            }
        }
    }
}

// ---------------- layer2 fc (K=128 -> OUT=4, H=1), one warp per node ---------
__global__ void gemm2_kernel(const float* __restrict__ h,
                             const float* __restrict__ W,
                             const float* __restrict__ al,
                             const float* __restrict__ ar,
                             float* __restrict__ feat2,
                             float* __restrict__ el,
                             float* __restrict__ er,
                             int base, int nEnd) {
    int warp = base + ((blockIdx.x * blockDim.x + threadIdx.x) >> 5);
    int lane = threadIdx.x & 31;
    if (warp >= nEnd) return;

    float a0 = 0.f, a1 = 0.f, a2 = 0.f, a3 = 0.f;
#pragma unroll
    for (int i = 0; i < 4; i++) {
        int k = lane + 32 * i;
        float hv = h[warp * 128 + k];
        const float4 w = *(const float4*)(W + k * 4);
        a0 += hv * w.x; a1 += hv * w.y; a2 += hv * w.z; a3 += hv * w.w;
    }
#pragma unroll
    for (int o = 16; o > 0; o >>= 1) {
        a0 += __shfl_xor_sync(0xFFFFFFFFu, a0, o);
        a1 += __shfl_xor_sync(0xFFFFFFFFu, a1, o);
        a2 += __shfl_xor_sync(0xFFFFFFFFu, a2, o);
        a3 += __shfl_xor_sync(0xFFFFFFFFu, a3, o);
    }
    if (lane == 0) {
        feat2[warp * 4 + 0] = a0;
        feat2[warp * 4 + 1] = a1;
        feat2[warp * 4 + 2] = a2;
        feat2[warp * 4 + 3] = a3;
        el[warp] = a0 * al[0] + a1 * al[1] + a2 * al[2] + a3 * al[3];
        er[warp] = a0 * ar[0] + a1 * ar[1] + a2 * ar[2] + a3 * ar[3];
    }
}

// ---------------- fused aggregation (layers 0,1): one warp per dst ------------
// R12-proven form; node range [base, nEnd).
__global__ void aggr_warp_kernel(const int* __restrict__ rowptr,
                                 const int* __restrict__ csrsrc,
                                 const float* __restrict__ el,
                                 const float* __restrict__ er,
                                 const float* __restrict__ feat,
                                 const float* __restrict__ bias,
                                 const float* __restrict__ resid,
                                 float* __restrict__ rst,
                                 int base, int nEnd, int applyAct) {
    int di = base + ((blockIdx.x * blockDim.x + threadIdx.x) >> 5);
    int lane = threadIdx.x & 31;
    if (di >= nEnd) return;

    int row0 = rowptr[di];
    int deg = rowptr[di + 1] - row0;
    int head = lane >> 3;
    float er_l = (lane < 4) ? er[di * 4 + lane] : 0.0f;

    float4 acc = make_float4(0.f, 0.f, 0.f, 0.f);
    float sexp = 0.0f;

    int e = 0;
    for (; e + 4 <= deg; e += 4) {
        int si0 = csrsrc[row0 + e];
        int si1 = csrsrc[row0 + e + 1];
        int si2 = csrsrc[row0 + e + 2];
        int si3 = csrsrc[row0 + e + 3];
        float x0 = 0.f, x1 = 0.f, x2 = 0.f, x3 = 0.f;
        if (lane < 4) {
            float v0 = el[si0 * 4 + lane] + er_l;
            float v1 = el[si1 * 4 + lane] + er_l;
            float v2 = el[si2 * 4 + lane] + er_l;
            float v3 = el[si3 * 4 + lane] + er_l;
            v0 = (v0 > 0.f) ? v0 : NEG_SLOPE * v0;
            v1 = (v1 > 0.f) ? v1 : NEG_SLOPE * v1;
            v2 = (v2 > 0.f) ? v2 : NEG_SLOPE * v2;
            v3 = (v3 > 0.f) ? v3 : NEG_SLOPE * v3;
            x0 = __expf(v0); x1 = __expf(v1);
            x2 = __expf(v2); x3 = __expf(v3);
        }
        float exa = __shfl_sync(0xFFFFFFFFu, x0, head);
        float exb = __shfl_sync(0xFFFFFFFFu, x1, head);
        float exc = __shfl_sync(0xFFFFFFFFu, x2, head);
        float exd = __shfl_sync(0xFFFFFFFFu, x3, head);
        const float4 fa = *(const float4*)(feat + si0 * 128 + lane * 4);
        const float4 fb = *(const float4*)(feat + si1 * 128 + lane * 4);
        const float4 fc = *(const float4*)(feat + si2 * 128 + lane * 4);
        const float4 fd = *(const float4*)(feat + si3 * 128 + lane * 4);
        acc.x += exa * fa.x + exb * fb.x + exc * fc.x + exd * fd.x;
        acc.y += exa * fa.y + exb * fb.y + exc * fc.y + exd * fd.y;
        acc.z += exa * fa.z + exb * fb.z + exc * fc.z + exd * fd.z;
        acc.w += exa * fa.w + exb * fb.w + exc * fc.w + exd * fd.w;
        sexp += exa + exb + exc + exd;
    }
    for (; e < deg; e++) {
        int si = csrsrc[row0 + e];
        float ex4 = 0.f;
        if (lane < 4) {
            float v = el[si * 4 + lane] + er_l;
            v = (v > 0.f) ? v : NEG_SLOPE * v;
            ex4 = __expf(v);
        }
        float ex = __shfl_sync(0xFFFFFFFFu, ex4, head);
        const float4 f = *(const float4*)(feat + si * 128 + lane * 4);
        acc.x += ex * f.x; acc.y += ex * f.y;
        acc.z += ex * f.z; acc.w += ex * f.w;
        sexp += ex;
    }

    float inv = (sexp > 0.0f) ? 1.0f / sexp : 0.0f;
    int idx = di * 128 + lane * 4;
    const float4 b4 = *(const float4*)(bias + lane * 4);
    float4 v = make_float4(acc.x * inv + b4.x, acc.y * inv + b4.y,
                           acc.z * inv + b4.z, acc.w * inv + b4.w);
    if (resid) {
        const float4 r4 = *(const float4*)(resid + idx);
        v.x += r4.x; v.y += r4.y; v.z += r4.z; v.w += r4.w;
    }
    if (applyAct) {
        v.x = (v.x > 0.f) ? v.x : (__expf(v.x) - 1.0f);
        v.y = (v.y > 0.f) ? v.y : (__expf(v.y) - 1.0f);
        v.z = (v.z > 0.f) ? v.z : (__expf(v.z) - 1.0f);
        v.w = (v.w > 0.f) ? v.w : (__expf(v.w) - 1.0f);
    }
    *(float4*)(rst + idx) = v;
}

// ---------------- fused aggregation (layer 2, H=1, D=4) ----------------------
__global__ void aggr2_kernel(const int* __restrict__ rowptr,
                             const int* __restrict__ csrsrc,
                             const float* __restrict__ el,
                             const float* __restrict__ er,
                             const float* __restrict__ feat2,
                             const float* __restrict__ bias,
                             float* __restrict__ out,
                             int N) {
    int di = (blockIdx.x * blockDim.x + threadIdx.x) >> 5;
    int lane = threadIdx.x & 31;
    if (di >= N) return;

    int row0 = rowptr[di];
    int deg = rowptr[di + 1] - row0;
    float erd = er[di];

    float a0 = 0.f, a1 = 0.f, a2 = 0.f, a3 = 0.f, sexp = 0.f;
    for (int e = lane; e < deg; e += 32) {
        int si = csrsrc[row0 + e];
        float v = el[si] + erd;
        v = (v > 0.f) ? v : NEG_SLOPE * v;
        float ex = __expf(v);
        const float4 f = *(const float4*)(feat2 + si * 4);
        a0 += ex * f.x; a1 += ex * f.y; a2 += ex * f.z; a3 += ex * f.w;
        sexp += ex;
    }
#pragma unroll
    for (int o = 16; o > 0; o >>= 1) {
        a0 += __shfl_xor_sync(0xFFFFFFFFu, a0, o);
        a1 += __shfl_xor_sync(0xFFFFFFFFu, a1, o);
        a2 += __shfl_xor_sync(0xFFFFFFFFu, a2, o);
        a3 += __shfl_xor_sync(0xFFFFFFFFu, a3, o);
        sexp += __shfl_xor_sync(0xFFFFFFFFu, sexp, o);
    }
    if (lane == 0) {
        float inv = (sexp > 0.0f) ? 1.0f / sexp : 0.0f;
        out[di * 4 + 0] = a0 * inv + bias[0];
        out[di * 4 + 1] = a1 * inv + bias[1];
        out[di * 4 + 2] = a2 * inv + bias[2];
        out[di * 4 + 3] = a3 * inv + bias[3];
    }
}

// ---------------- host launcher ----------------------------------------------
extern "C" void kernel_launch(void* const* d_in, const int* in_sizes, int n_in,
                              void* d_out, int out_size) {
    const float* x   = (const float*)d_in[0];
    const int*   src = (const int*)d_in[1];
    const int*   dst = (const int*)d_in[2];
    const float* W0  = (const float*)d_in[3];
    const float* al0 = (const float*)d_in[4];
    const float* ar0 = (const float*)d_in[5];
    const float* b0  = (const float*)d_in[6];
    const float* W1  = (const float*)d_in[7];
    const float* al1 = (const float*)d_in[8];
    const float* ar1 = (const float*)d_in[9];
    const float* b1  = (const float*)d_in[10];
    const float* W2  = (const float*)d_in[11];
    const float* al2 = (const float*)d_in[12];
    const float* ar2 = (const float*)d_in[13];
    const float* b2  = (const float*)d_in[14];

    int N = in_sizes[0] / 64;
    int E = in_sizes[1];

    float *feat, *rstA, *rstB, *el, *er, *feat2;
    int *count, *rowptr, *cursor, *csrsrc;
    cudaGetSymbolAddress((void**)&feat,   g_feat);
    cudaGetSymbolAddress((void**)&rstA,   g_rstA);
    cudaGetSymbolAddress((void**)&rstB,   g_rstB);
    cudaGetSymbolAddress((void**)&el,     g_el);
    cudaGetSymbolAddress((void**)&er,     g_er);
    cudaGetSymbolAddress((void**)&feat2,  g_feat2);
    cudaGetSymbolAddress((void**)&count,  g_count);
    cudaGetSymbolAddress((void**)&rowptr, g_rowptr);
    cudaGetSymbolAddress((void**)&cursor, g_cursor);
    cudaGetSymbolAddress((void**)&csrsrc, g_csrsrc);

    float* out = (float*)d_out;

    const int TB = 256;
    int gridE = (E + TB - 1) / TB;

    // node split (64-aligned) for cross-layer pipelining
    int NH = ((N / 2) + 63) & ~63;
    if (NH > N) NH = N;
    int NB = N - NH;

    int gridGemmA = (NH + 63) / 64;
    int gridGemmB = (NB + 63) / 64;
    int gridAggrA = (NH * 32 + TB - 1) / TB;
    int gridAggrB = (NB * 32 + TB - 1) / TB;
    int gridW2A   = (NH * 32 + TB - 1) / TB;
    int gridW2B   = (NB * 32 + TB - 1) / TB;
    int gridWarpN = (N * 32 + TB - 1) / TB;

    int smemTC = SM_TOTAL_F * sizeof(uint32_t);   // 53248 B
    cudaFuncSetAttribute(gemm_attn_tc<64>,
                         cudaFuncAttributeMaxDynamicSharedMemorySize, smemTC);
    cudaFuncSetAttribute(gemm_attn_tc<128>,
                         cudaFuncAttributeMaxDynamicSharedMemorySize, smemTC);

    cudaStream_t s2 = 0;
    cudaEvent_t evA = 0, evCsr = 0, evG0 = 0, evA0B = 0, evG1B = 0, evA1B = 0;
    bool forked =
        (cudaStreamCreateWithFlags(&s2, cudaStreamNonBlocking) == cudaSuccess) &&
        (cudaEventCreateWithFlags(&evA,   cudaEventDisableTiming) == cudaSuccess) &&
        (cudaEventCreateWithFlags(&evCsr, cudaEventDisableTiming) == cudaSuccess) &&
        (cudaEventCreateWithFlags(&evG0,  cudaEventDisableTiming) == cudaSuccess) &&
        (cudaEventCreateWithFlags(&evA0B, cudaEventDisableTiming) == cudaSuccess) &&
        (cudaEventCreateWithFlags(&evG1B, cudaEventDisableTiming) == cudaSuccess) &&
        (cudaEventCreateWithFlags(&evA1B, cudaEventDisableTiming) == cudaSuccess);

    if (forked) {
        // fork CSR build onto s2, overlapped with layer-0 gemm on s0
        cudaEventRecord(evA, 0);
        cudaStreamWaitEvent(s2, evA, 0);
        cudaMemsetAsync(count, 0, N * sizeof(int), s2);
        count_kernel<<<gridE, TB, 0, s2>>>(dst, count, E);
        scan_kernel<<<1, 1024, 0, s2>>>(count, rowptr, cursor, N);
        fill_csr_kernel<<<gridE, TB, 0, s2>>>(src, dst, cursor, csrsrc, E);
        cudaEventRecord(evCsr, s2);

        gemm_attn_tc<64><<<gridGemmA + gridGemmB, 256, smemTC>>>(
            x, W0, al0, ar0, feat, el, er, 0, N);
        cudaStreamWaitEvent(0, evCsr, 0);
        cudaEventRecord(evG0, 0);                      // gemm0 + CSR complete

        // aggr0 split: A on s0, B on s2 (overlaps later with gemm1_A)
        cudaStreamWaitEvent(s2, evG0, 0);
        aggr_warp_kernel<<<gridAggrA, TB>>>(rowptr, csrsrc, el, er, feat,
                                            b0, nullptr, rstA, 0, NH, 1);
        aggr_warp_kernel<<<gridAggrB, TB, 0, s2>>>(rowptr, csrsrc, el, er, feat,
                                                   b0, nullptr, rstA, NH, N, 1);
        cudaEventRecord(evA0B, s2);

        // gemm1_A overlaps aggr0_B
        gemm_attn_tc<128><<<gridGemmA, 256, smemTC>>>(
            rstA, W1, al1, ar1, feat, el, er, 0, NH);
        cudaStreamWaitEvent(0, evA0B, 0);
        gemm_attn_tc<128><<<gridGemmB, 256, smemTC>>>(
            rstA, W1, al1, ar1, feat, el, er, NH, N);
        cudaEventRecord(evG1B, 0);                     // gemm1 fully done

        // aggr1 split: A on s0, B on s2 (overlaps later with gemm2_A)
        cudaStreamWaitEvent(s2, evG1B, 0);
        aggr_warp_kernel<<<gridAggrA, TB>>>(rowptr, csrsrc, el, er, feat,
                                            b1, rstA, rstB, 0, NH, 1);
        aggr_warp_kernel<<<gridAggrB, TB, 0, s2>>>(rowptr, csrsrc, el, er, feat,
                                                   b1, rstA, rstB, NH, N, 1);
        cudaEventRecord(evA1B, s2);

        // gemm2_A overlaps aggr1_B
        gemm2_kernel<<<gridW2A, TB>>>(rstB, W2, al2, ar2, feat2, el, er, 0, NH);
        cudaStreamWaitEvent(0, evA1B, 0);
        gemm2_kernel<<<gridW2B, TB>>>(rstB, W2, al2, ar2, feat2, el, er, NH, N);

        aggr2_kernel<<<gridWarpN, TB>>>(rowptr, csrsrc, el, er, feat2, b2, out, N);
    } else {
        // sequential fallback
        cudaMemsetAsync(count, 0, N * sizeof(int));
        count_kernel<<<gridE, TB>>>(dst, count, E);
        scan_kernel<<<1, 1024>>>(count, rowptr, cursor, N);
        fill_csr_kernel<<<gridE, TB>>>(src, dst, cursor, csrsrc, E);
        gemm_attn_tc<64><<<gridGemmA + gridGemmB, 256, smemTC>>>(
            x, W0, al0, ar0, feat, el, er, 0, N);
        aggr_warp_kernel<<<gridWarpN, TB>>>(rowptr, csrsrc, el, er, feat,
                                            b0, nullptr, rstA, 0, N, 1);
        gemm_attn_tc<128><<<gridGemmA + gridGemmB, 256, smemTC>>>(
            rstA, W1, al1, ar1, feat, el, er, 0, N);
        aggr_warp_kernel<<<gridWarpN, TB>>>(rowptr, csrsrc, el, er, feat,
                                            b1, rstA, rstB, 0, N, 1);
        gemm2_kernel<<<gridWarpN, TB>>>(rstB, W2, al2, ar2, feat2, el, er, 0, N);
        aggr2_kernel<<<gridWarpN, TB>>>(rowptr, csrsrc, el, er, feat2, b2, out, N);
    }
}